// round 17
// baseline (speedup 1.0000x reference)
#include <cuda_runtime.h>
#include <cuda_bf16.h>
#include <cuda_fp8.h>
#include <cstdint>
#include <math.h>

namespace {
constexpr int kB   = 4;
constexpr int kLq  = 512;
constexpr int kLkv = 2048;
constexpr int kDim = 1024;
constexpr int kH   = 16;
constexpr int kMlp = 4096;
constexpr int kNQ  = kB * kLq;    // 2048
constexpr int kNKV = kB * kLkv;   // 8192
constexpr int kSplits = 2;
constexpr int kLsStride = kNQ * kH;
constexpr size_t kOpStride = (size_t)kNQ * kDim;
constexpr float kWScale = 16.0f;       // weight pre-scale into e4m3 range
constexpr float kInvWScale = 0.0625f;  // folded out in epilogues
}

__device__ __align__(256) unsigned char g_scratch[160u * 1024u * 1024u];

#define CP_ASYNC16(dst, src) \
    asm volatile("cp.async.cg.shared.global [%0], [%1], 16;" :: "r"(dst), "l"(src))
#define CP_COMMIT() asm volatile("cp.async.commit_group;")
#define LDSM4(r0,r1,r2,r3,addr) \
    asm volatile("ldmatrix.sync.aligned.m8n8.x4.shared.b16 {%0,%1,%2,%3}, [%4];" \
        : "=r"(r0),"=r"(r1),"=r"(r2),"=r"(r3) : "r"(addr))
#define LDSM4T(r0,r1,r2,r3,addr) \
    asm volatile("ldmatrix.sync.aligned.m8n8.x4.trans.shared.b16 {%0,%1,%2,%3}, [%4];" \
        : "=r"(r0),"=r"(r1),"=r"(r2),"=r"(r3) : "r"(addr))
#define MMA16816(d,a0,a1,a2,a3,b0,b1) \
    asm volatile("mma.sync.aligned.m16n8k16.row.col.f32.bf16.bf16.f32 " \
        "{%0,%1,%2,%3}, {%4,%5,%6,%7}, {%8,%9}, {%0,%1,%2,%3};" \
        : "+f"(d[0]),"+f"(d[1]),"+f"(d[2]),"+f"(d[3]) \
        : "r"(a0),"r"(a1),"r"(a2),"r"(a3),"r"(b0),"r"(b1))
#define MMA16832F8(d,a0,a1,a2,a3,b0,b1) \
    asm volatile("mma.sync.aligned.m16n8k32.row.col.f32.e4m3.e4m3.f32 " \
        "{%0,%1,%2,%3}, {%4,%5,%6,%7}, {%8,%9}, {%0,%1,%2,%3};" \
        : "+f"(d[0]),"+f"(d[1]),"+f"(d[2]),"+f"(d[3]) \
        : "r"(a0),"r"(a1),"r"(a2),"r"(a3),"r"(b0),"r"(b1))
#define HFMA2BF(d,x,a,c) \
    asm("fma.rn.bf16x2 %0, %1, %2, %3;" : "=r"(d) : "r"(x), "r"(a), "r"(c))

__device__ __forceinline__ uint32_t pack_bf16(float a, float b) {
    __nv_bfloat162 t = __floats2bfloat162_rn(a, b);
    return *reinterpret_cast<uint32_t*>(&t);
}
__device__ __forceinline__ uint16_t pack_fp8(float a, float b) {
    return (uint16_t)__nv_cvt_float2_to_fp8x2(make_float2(a, b),
                                              __NV_SATFINITE, __NV_E4M3);
}
__device__ __forceinline__ uint32_t pack_fp8x4(float a, float b, float c, float d) {
    return (uint32_t)pack_fp8(a, b) | ((uint32_t)pack_fp8(c, d) << 16);
}

// ---------------------------------------------------------------------------
// Merged f32 -> fp8(e4m3, x16) weight convert
// dst layout (elements): Wq@0, Wk@1M, Wv@2M, Wo@3M, fc1@4M, fc2@8M
// ---------------------------------------------------------------------------
__global__ __launch_bounds__(256) void cvt_all_kernel(
    const float* __restrict__ Wq, const float* __restrict__ Wk,
    const float* __restrict__ Wv, const float* __restrict__ Wo,
    const float* __restrict__ fc1, const float* __restrict__ fc2,
    uint8_t* __restrict__ dst)
{
    const size_t M1 = 1u << 20;
    size_t gid = (size_t)blockIdx.x * 1024 + threadIdx.x * 4;
    const float* src; size_t off;
    if (gid < 4 * M1) {
        int si = (int)(gid >> 20);
        src = (si == 0) ? Wq : (si == 1) ? Wk : (si == 2) ? Wv : Wo;
        off = gid & (M1 - 1);
    } else if (gid < 8 * M1) { src = fc1; off = gid - 4 * M1; }
    else                     { src = fc2; off = gid - 8 * M1; }
    float4 v = *reinterpret_cast<const float4*>(src + off);
    *reinterpret_cast<uint32_t*>(dst + gid) =
        pack_fp8x4(v.x * kWScale, v.y * kWScale, v.z * kWScale, v.w * kWScale);
}

// ---------------------------------------------------------------------------
// LayerNorm core (fp32 -> fp8), one block per row
// ---------------------------------------------------------------------------
__device__ __forceinline__ void ln_row(
    const float* __restrict__ xr, const float* __restrict__ wv4,
    const float* __restrict__ bv4, uint8_t* __restrict__ yr)
{
    int t = threadIdx.x;
    float4 xv = reinterpret_cast<const float4*>(xr)[t];
    float s  = xv.x + xv.y + xv.z + xv.w;
    float s2 = xv.x*xv.x + xv.y*xv.y + xv.z*xv.z + xv.w*xv.w;

    #pragma unroll
    for (int off = 16; off > 0; off >>= 1) {
        s  += __shfl_xor_sync(0xffffffffu, s,  off);
        s2 += __shfl_xor_sync(0xffffffffu, s2, off);
    }
    __shared__ float rs[8], rs2[8];
    int wid = t >> 5;
    if ((t & 31) == 0) { rs[wid] = s; rs2[wid] = s2; }
    __syncthreads();
    s = 0.f; s2 = 0.f;
    #pragma unroll
    for (int i = 0; i < 8; i++) { s += rs[i]; s2 += rs2[i]; }

    float mu  = s * (1.0f / kDim);
    float var = s2 * (1.0f / kDim) - mu * mu;
    float r   = rsqrtf(var + 1e-6f);

    float4 wv = reinterpret_cast<const float4*>(wv4)[t];
    float4 bv = reinterpret_cast<const float4*>(bv4)[t];
    *reinterpret_cast<uint32_t*>(yr + 4 * t) =
        pack_fp8x4((xv.x - mu) * r * wv.x + bv.x,
                   (xv.y - mu) * r * wv.y + bv.y,
                   (xv.z - mu) * r * wv.z + bv.z,
                   (xv.w - mu) * r * wv.w + bv.w);
}

__global__ __launch_bounds__(256) void ln_fp8_kernel(
    const float* __restrict__ x, const float* __restrict__ w,
    const float* __restrict__ b, uint8_t* __restrict__ y)
{
    int row = blockIdx.x;
    ln_row(x + (size_t)row * kDim, w, b, y + (size_t)row * kDim);
}

__global__ __launch_bounds__(256) void ln_qkv_kernel(
    const float* __restrict__ qx, const float* __restrict__ kvx,
    const float* __restrict__ qw, const float* __restrict__ qb_,
    const float* __restrict__ kvw, const float* __restrict__ kvb,
    uint8_t* __restrict__ qy, uint8_t* __restrict__ kvy)
{
    int row = blockIdx.x;
    if (row < kNQ) {
        ln_row(qx + (size_t)row * kDim, qw, qb_, qy + (size_t)row * kDim);
    } else {
        int r = row - kNQ;
        ln_row(kvx + (size_t)r * kDim, kvw, kvb, kvy + (size_t)r * kDim);
    }
}

// ---------------------------------------------------------------------------
// fp8 GEMM core: C[.,N] = A @ W^T, e4m3 inputs (W pre-scaled x16), fp32 accum.
// 128 threads, 4 warps (2x2), warp tile 64 x BN/2, BK=128 fp8 (= 128B rows,
// same cp.async/swizzle/ldmatrix addressing as the bf16 k64 version),
// 3-stage cp.async, one barrier per k-iter.  acc is 16x true value.
// EPI 1: fp8 GELU(acc/16+bias) -> C8.  EPI 2: fp32 res + alpha*(acc/16+bias).
// EPI 3: bf16, per-64-col L2-norm*scale (scale-invariant) if do_norm,
//        else plain*(1/16).
// ---------------------------------------------------------------------------
template <int EPI, int BN>
__device__ __forceinline__ void gemm_core(
    const uint8_t* __restrict__ A, const uint8_t* __restrict__ W,
    int N, int K, long m0, long n0,
    const float* __restrict__ bias, const float* __restrict__ res,
    const float* __restrict__ alpha,
    float* __restrict__ Cf, __nv_bfloat16* __restrict__ Cb,
    uint8_t* __restrict__ C8,
    bool do_norm, float nscale, uint32_t smem)
{
    constexpr int NW   = BN / 2;
    constexpr int NFR  = NW / 8;
    constexpr int NB16 = NW / 16;
    constexpr uint32_t kStageBytes = (uint32_t)(128 + BN) * 128u;
    constexpr uint32_t kBOff = 128u * 128u;
    constexpr int LITER = (128 + BN) / 16;

    const int tid  = threadIdx.x;
    const int lane = tid & 31;
    const int w    = tid >> 5;
    const int wr   = (w >> 1) * 64;
    const int wc   = (w & 1) * NW;

    const uint8_t* Ag = A + m0 * K;
    const uint8_t* Wg = W + n0 * K;

    auto load_tile = [&](int t, int s) {
        uint32_t sA = smem + (uint32_t)s * kStageBytes;
        uint32_t sB = sA + kBOff;
        const uint8_t* a = Ag + (long)t * 128;
        const uint8_t* b = Wg + (long)t * 128;
        #pragma unroll
        for (int p = 0; p < LITER; p++) {
            int idx = tid + p * 128;
            int row = idx >> 3, ch = idx & 7;
            if (row < 128) {
                uint32_t doff = row * 128 + ((uint32_t)(ch ^ (row & 7)) << 4);
                CP_ASYNC16(sA + doff, a + (long)row * K + ch * 16);
            } else {
                int r = row - 128;
                uint32_t doff = r * 128 + ((uint32_t)(ch ^ (r & 7)) << 4);
                CP_ASYNC16(sB + doff, b + (long)r * K + ch * 16);
            }
        }
    };

    float acc[4][NFR][4];
    #pragma unroll
    for (int i = 0; i < 4; i++)
        #pragma unroll
        for (int j = 0; j < NFR; j++)
            #pragma unroll
            for (int c = 0; c < 4; c++) acc[i][j][c] = 0.f;

    const int T = K >> 7;   // BK = 128 fp8

    load_tile(0, 0); CP_COMMIT();
    load_tile(1, 1); CP_COMMIT();

    for (int kt = 0; kt < T; kt++) {
        int s = kt % 3;
        asm volatile("cp.async.wait_group 1;" ::: "memory");
        __syncthreads();

        if (kt + 2 < T) load_tile(kt + 2, (kt + 2) % 3);
        CP_COMMIT();

        uint32_t sA = smem + (uint32_t)s * kStageBytes;
        uint32_t sB = sA + kBOff;
        #pragma unroll
        for (int ks = 0; ks < 4; ks++) {   // each ks = k32 fp8 = 32B = 2 chunks
            uint32_t afr[4][4];
            #pragma unroll
            for (int im = 0; im < 4; im++) {
                int row = wr + im * 16 + (lane & 15);
                int ch  = ks * 2 + (lane >> 4);
                uint32_t addr = sA + row * 128 + ((uint32_t)(ch ^ (row & 7)) << 4);
                LDSM4(afr[im][0], afr[im][1], afr[im][2], afr[im][3], addr);
            }
            uint32_t bfr[NFR][2];
            #pragma unroll
            for (int ib = 0; ib < NB16; ib++) {
                int row = wc + ib * 16 + ((lane >> 4) << 3) + (lane & 7);
                int ch  = ks * 2 + ((lane >> 3) & 1);
                uint32_t addr = sB + row * 128 + ((uint32_t)(ch ^ (row & 7)) << 4);
                uint32_t r0, r1, r2, r3;
                LDSM4(r0, r1, r2, r3, addr);
                bfr[2*ib][0] = r0; bfr[2*ib][1] = r1;
                bfr[2*ib+1][0] = r2; bfr[2*ib+1][1] = r3;
            }
            #pragma unroll
            for (int im = 0; im < 4; im++)
                #pragma unroll
                for (int in = 0; in < NFR; in++)
                    MMA16832F8(acc[im][in], afr[im][0], afr[im][1], afr[im][2], afr[im][3],
                               bfr[in][0], bfr[in][1]);
        }
    }

    const int g = lane >> 2, tg = lane & 3;
    const float al = (EPI == 2) ? alpha[0] : 0.f;
    #pragma unroll
    for (int im = 0; im < 4; im++) {
        long r0 = m0 + wr + im * 16 + g;
        float inv0 = kInvWScale, inv1 = kInvWScale;
        if (EPI == 3 && do_norm) {
            float ss0 = 0.f, ss1 = 0.f;
            #pragma unroll
            for (int in = 0; in < NFR; in++) {
                ss0 += acc[im][in][0]*acc[im][in][0] + acc[im][in][1]*acc[im][in][1];
                ss1 += acc[im][in][2]*acc[im][in][2] + acc[im][in][3]*acc[im][in][3];
            }
            ss0 += __shfl_xor_sync(0xffffffffu, ss0, 1);
            ss0 += __shfl_xor_sync(0xffffffffu, ss0, 2);
            ss1 += __shfl_xor_sync(0xffffffffu, ss1, 1);
            ss1 += __shfl_xor_sync(0xffffffffu, ss1, 2);
            inv0 = nscale / fmaxf(sqrtf(ss0), 1e-6f);   // scale-invariant
            inv1 = nscale / fmaxf(sqrtf(ss1), 1e-6f);
        }
        #pragma unroll
        for (int in = 0; in < NFR; in++) {
            long c = n0 + wc + in * 8 + tg * 2;
            float v0 = acc[im][in][0], v1 = acc[im][in][1];
            float v2 = acc[im][in][2], v3 = acc[im][in][3];
            if (EPI == 1) {
                float b0 = bias[c], b1 = bias[c + 1];
                v0 = fmaf(v0, kInvWScale, b0); v1 = fmaf(v1, kInvWScale, b1);
                v2 = fmaf(v2, kInvWScale, b0); v3 = fmaf(v3, kInvWScale, b1);
                const float is2 = 0.7071067811865475f;
                v0 = 0.5f * v0 * (1.f + erff(v0 * is2));
                v1 = 0.5f * v1 * (1.f + erff(v1 * is2));
                v2 = 0.5f * v2 * (1.f + erff(v2 * is2));
                v3 = 0.5f * v3 * (1.f + erff(v3 * is2));
                *reinterpret_cast<uint16_t*>(&C8[r0 * N + c])       = pack_fp8(v0, v1);
                *reinterpret_cast<uint16_t*>(&C8[(r0 + 8) * N + c]) = pack_fp8(v2, v3);
            } else if (EPI == 2) {
                float b0 = bias[c], b1 = bias[c + 1];
                float2 ra = *reinterpret_cast<const float2*>(&res[r0 * N + c]);
                float2 rb = *reinterpret_cast<const float2*>(&res[(r0 + 8) * N + c]);
                *reinterpret_cast<float2*>(&Cf[r0 * N + c]) =
                    make_float2(ra.x + al * fmaf(v0, kInvWScale, b0),
                                ra.y + al * fmaf(v1, kInvWScale, b1));
                *reinterpret_cast<float2*>(&Cf[(r0 + 8) * N + c]) =
                    make_float2(rb.x + al * fmaf(v2, kInvWScale, b0),
                                rb.y + al * fmaf(v3, kInvWScale, b1));
            } else {  // EPI 3 (bf16 out)
                *reinterpret_cast<__nv_bfloat162*>(&Cb[r0 * N + c]) =
                    __floats2bfloat162_rn(v0 * inv0, v1 * inv0);
                *reinterpret_cast<__nv_bfloat162*>(&Cb[(r0 + 8) * N + c]) =
                    __floats2bfloat162_rn(v2 * inv1, v3 * inv1);
            }
        }
    }
}

template <int EPI, int BN>
__global__ __launch_bounds__(128) void gemm_fp8_kernel(
    const uint8_t* __restrict__ A, const uint8_t* __restrict__ W,
    int N, int K,
    const float* __restrict__ bias, const float* __restrict__ res,
    const float* __restrict__ alpha,
    float* __restrict__ Cf, __nv_bfloat16* __restrict__ Cb,
    uint8_t* __restrict__ C8)
{
    extern __shared__ __align__(1024) char smraw[];
    uint32_t smem = (uint32_t)__cvta_generic_to_shared(smraw);
    long m0 = (long)blockIdx.y << 7;
    long n0 = (long)blockIdx.x * BN;
    gemm_core<EPI, BN>(A, W, N, K, m0, n0, bias, res, alpha, Cf, Cb, C8,
                       false, 1.f, smem);
}

// merged Q/K/V projection: grid = 128 (Q) + 512 (K) + 512 (V), bf16 outputs.
// Q l2norm*0.5 (1/TAU pre-folded); K l2norm; V plain (/16 weight unscale).
__global__ __launch_bounds__(128) void qkv_gemm_kernel(
    const uint8_t* __restrict__ qn, const uint8_t* __restrict__ kvn,
    const uint8_t* __restrict__ Wqb, const uint8_t* __restrict__ Wkb,
    const uint8_t* __restrict__ Wvb,
    __nv_bfloat16* __restrict__ qb, __nv_bfloat16* __restrict__ kb,
    __nv_bfloat16* __restrict__ vb)
{
    extern __shared__ __align__(1024) char smraw[];
    uint32_t smem = (uint32_t)__cvta_generic_to_shared(smraw);

    int bid = blockIdx.x;
    const uint8_t *A, *W;
    __nv_bfloat16* C;
    int rel; bool do_norm; float sc;
    if (bid < 128)      { A = qn;  W = Wqb; C = qb; rel = bid;       do_norm = true;  sc = 0.5f; }
    else if (bid < 640) { A = kvn; W = Wkb; C = kb; rel = bid - 128; do_norm = true;  sc = 1.0f; }
    else                { A = kvn; W = Wvb; C = vb; rel = bid - 640; do_norm = false; sc = 1.0f; }
    long n0 = (long)(rel & 7) << 7;
    long m0 = (long)(rel >> 3) << 7;
    gemm_core<3, 128>(A, W, kDim, kDim, m0, n0, nullptr, nullptr, nullptr,
                      nullptr, C, nullptr, do_norm, sc, smem);
}

// ---------------------------------------------------------------------------
// Split-KV flash attention (bf16, unchanged from R16). Scores in [-0.5,0.5];
// exp via bf16x2 cubic; denominator via ones-MMA; additive split partials.
// Grid (B*H, Lq/64, kSplits), 128 threads.
// ---------------------------------------------------------------------------
__global__ __launch_bounds__(128) void attn_mma_kernel(
    const __nv_bfloat16* __restrict__ q, const __nv_bfloat16* __restrict__ k,
    const __nv_bfloat16* __restrict__ v,
    float* __restrict__ opart, float* __restrict__ lpart)
{
    __shared__ __align__(1024) unsigned char sm[40 * 1024];
    const uint32_t smem = (uint32_t)__cvta_generic_to_shared(sm);
    const uint32_t sQ = smem;

    const int bh = blockIdx.x;
    const int b = bh >> 4, h = bh & 15;
    const int q0 = blockIdx.y * 64;
    const int sp = blockIdx.z;
    const int tid = threadIdx.x;
    const int lane = tid & 31;
    const int w = tid >> 5;

    const int kv0base = sp * (kLkv / kSplits);

    const __nv_bfloat16* qg = q + ((size_t)(b * kLq + q0)) * kDim + h * 64;
    const __nv_bfloat16* kg = k + ((size_t)(b * kLkv + kv0base)) * kDim + h * 64;
    const __nv_bfloat16* vg = v + ((size_t)(b * kLkv + kv0base)) * kDim + h * 64;

    #pragma unroll
    for (int p = 0; p < 4; p++) {
        int idx = tid + p * 128;
        int row = idx >> 3, ch = idx & 7;
        uint32_t doff = row * 128 + ((uint32_t)(ch ^ (row & 7)) << 4);
        CP_ASYNC16(sQ + doff, qg + (size_t)row * kDim + ch * 8);
        CP_ASYNC16(sQ + 8192 + doff, kg + (size_t)row * kDim + ch * 8);
        CP_ASYNC16(sQ + 16384 + doff, vg + (size_t)row * kDim + ch * 8);
    }
    CP_COMMIT();

    const uint32_t C_ONE = 0x3F803F80u;
    const uint32_t C2 = pack_bf16(0.51056f, 0.51056f);
    const uint32_t C3 = pack_bf16(0.16928f, 0.16928f);

    uint32_t qa[4][4];
    float oacc[8][4];
    #pragma unroll
    for (int j = 0; j < 8; j++)
        #pragma unroll
        for (int c = 0; c < 4; c++) oacc[j][c] = 0.f;
    float sumacc[4] = {0.f, 0.f, 0.f, 0.f};

    const int T = kLkv / kSplits / 64;
    for (int t = 0; t < T; t++) {
        int s = t & 1;
        if (t + 1 < T) {
            uint32_t sK = sQ + 8192 + (s ^ 1) * 16384;
            uint32_t sV = sK + 8192;
            const __nv_bfloat16* kp = kg + (size_t)(t + 1) * 64 * kDim;
            const __nv_bfloat16* vp = vg + (size_t)(t + 1) * 64 * kDim;
            #pragma unroll
            for (int p = 0; p < 4; p++) {
                int idx = tid + p * 128;
                int row = idx >> 3, ch = idx & 7;
                uint32_t doff = row * 128 + ((uint32_t)(ch ^ (row & 7)) << 4);
                CP_ASYNC16(sK + doff, kp + (size_t)row * kDim + ch * 8);
                CP_ASYNC16(sV + doff, vp + (size_t)row * kDim + ch * 8);
            }
            CP_COMMIT();
            asm volatile("cp.async.wait_group 1;");
        } else {
            asm volatile("cp.async.wait_group 0;");
        }
        __syncthreads();

        if (t == 0) {
            #pragma unroll
            for (int ks = 0; ks < 4; ks++) {
                int row = w * 16 + (lane & 15);
                int ch  = ks * 2 + (lane >> 4);
                uint32_t addr = sQ + row * 128 + ((uint32_t)(ch ^ (row & 7)) << 4);
                LDSM4(qa[ks][0], qa[ks][1], qa[ks][2], qa[ks][3], addr);
            }
        }

        uint32_t sK = sQ + 8192 + s * 16384;
        uint32_t sV = sK + 8192;

        float sacc[8][4];
        #pragma unroll
        for (int j = 0; j < 8; j++)
            #pragma unroll
            for (int c = 0; c < 4; c++) sacc[j][c] = 0.f;

        #pragma unroll
        for (int ks = 0; ks < 4; ks++) {
            uint32_t bfr[8][2];
            #pragma unroll
            for (int ib = 0; ib < 4; ib++) {
                int row = ib * 16 + ((lane >> 4) << 3) + (lane & 7);
                int ch  = ks * 2 + ((lane >> 3) & 1);
                uint32_t addr = sK + row * 128 + ((uint32_t)(ch ^ (row & 7)) << 4);
                uint32_t r0, r1, r2, r3;
                LDSM4(r0, r1, r2, r3, addr);
                bfr[2*ib][0] = r0; bfr[2*ib][1] = r1;
                bfr[2*ib+1][0] = r2; bfr[2*ib+1][1] = r3;
            }
            #pragma unroll
            for (int j = 0; j < 8; j++)
                MMA16816(sacc[j], qa[ks][0], qa[ks][1], qa[ks][2], qa[ks][3],
                         bfr[j][0], bfr[j][1]);
        }

        uint32_t pa[4][4];
        #pragma unroll
        for (int kc = 0; kc < 4; kc++) {
            pa[kc][0] = pack_bf16(sacc[2*kc][0],   sacc[2*kc][1]);
            pa[kc][1] = pack_bf16(sacc[2*kc][2],   sacc[2*kc][3]);
            pa[kc][2] = pack_bf16(sacc[2*kc+1][0], sacc[2*kc+1][1]);
            pa[kc][3] = pack_bf16(sacc[2*kc+1][2], sacc[2*kc+1][3]);
        }
        #pragma unroll
        for (int kc = 0; kc < 4; kc++)
            #pragma unroll
            for (int r = 0; r < 4; r++) {
                uint32_t x = pa[kc][r], tpoly;
                HFMA2BF(tpoly, x, C3, C2);
                HFMA2BF(tpoly, x, tpoly, C_ONE);
                HFMA2BF(tpoly, x, tpoly, C_ONE);
                pa[kc][r] = tpoly;
            }

        const int mi = lane >> 3;
        #pragma unroll
        for (int kc = 0; kc < 4; kc++) {
            MMA16816(sumacc, pa[kc][0], pa[kc][1], pa[kc][2], pa[kc][3],
                     C_ONE, C_ONE);
            #pragma unroll
            for (int ng = 0; ng < 4; ng++) {
                int row = kc * 16 + ((mi & 1) << 3) + (lane & 7);
                int ch  = ng * 2 + (mi >> 1);
                uint32_t addr = sV + row * 128 + ((uint32_t)(ch ^ (row & 7)) << 4);
                uint32_t r0, r1, r2, r3;
                LDSM4T(r0, r1, r2, r3, addr);
                MMA16816(oacc[2*ng],   pa[kc][0], pa[kc][1], pa[kc][2], pa[kc][3], r0, r1);
                MMA16816(oacc[2*ng+1], pa[kc][0], pa[kc][1], pa[kc][2], pa[kc][3], r2, r3);
            }
        }
        __syncthreads();
    }

    const int g = lane >> 2, tg = lane & 3;
    const size_t rowA = (size_t)(b * kLq + q0 + w * 16 + g);
    float* op = opart + (size_t)sp * kOpStride + rowA * kDim + h * 64;
    #pragma unroll
    for (int j = 0; j < 8; j++) {
        int c = j * 8 + tg * 2;
        *reinterpret_cast<float2*>(op + c) = make_float2(oacc[j][0], oacc[j][1]);
        *reinterpret_cast<float2*>(op + 8 * kDim + c) = make_float2(oacc[j][2], oacc[j][3]);
    }
    if (tg == 0) {
        lpart[sp * kLsStride + rowA * kH + h]       = sumacc[0];
        lpart[sp * kLsStride + (rowA + 8) * kH + h] = sumacc[2];
    }
}

// combine: ctx[row, c] = (N0 + N1) / (l0 + l1), fp8 out (feeds Wo fp8 GEMM).
__global__ __launch_bounds__(256) void attn_combine_kernel(
    const float* __restrict__ opart, const float* __restrict__ lpart,
    uint8_t* __restrict__ ctx)
{
    const size_t row = blockIdx.x;
    const int c0 = threadIdx.x * 4;
    const int h = c0 >> 6;
    float l = lpart[row * kH + h] + lpart[kLsStride + row * kH + h];
    float inv = 1.0f / l;
    float4 a = *reinterpret_cast<const float4*>(opart + row * kDim + c0);
    float4 bb = *reinterpret_cast<const float4*>(opart + kOpStride + row * kDim + c0);
    *reinterpret_cast<uint32_t*>(ctx + row * kDim + c0) =
        pack_fp8x4((a.x + bb.x) * inv, (a.y + bb.y) * inv,
                   (a.z + bb.z) * inv, (a.w + bb.w) * inv);
}

// ---------------------------------------------------------------------------
// kernel_launch
// ---------------------------------------------------------------------------
extern "C" void kernel_launch(void* const* d_in, const int* in_sizes, int n_in,
                              void* d_out, int out_size)
{
    const float* q_tokens   = (const float*)d_in[0];
    const float* kv_tokens  = (const float*)d_in[1];
    const float* q_ln_w     = (const float*)d_in[2];
    const float* q_ln_b     = (const float*)d_in[3];
    const float* kv_ln_w    = (const float*)d_in[4];
    const float* kv_ln_b    = (const float*)d_in[5];
    const float* mlp_ln_w   = (const float*)d_in[6];
    const float* mlp_ln_b   = (const float*)d_in[7];
    const float* Wq         = (const float*)d_in[8];
    const float* Wk         = (const float*)d_in[9];
    const float* Wv         = (const float*)d_in[10];
    const float* Wo         = (const float*)d_in[11];
    const float* bo         = (const float*)d_in[12];
    const float* fc1_w      = (const float*)d_in[13];
    const float* fc1_b      = (const float*)d_in[14];
    const float* fc2_w      = (const float*)d_in[15];
    const float* fc2_b      = (const float*)d_in[16];
    const float* alpha_attn = (const float*)d_in[17];
    const float* alpha_mlp  = (const float*)d_in[18];
    float* out = (float*)d_out;

    unsigned char* arena = nullptr;
    cudaGetSymbolAddress((void**)&arena, g_scratch);
    const size_t MB = 1024u * 1024u;

    uint8_t*       qn   = (uint8_t*)(arena + 0 * MB);    // 2 MB fp8
    uint8_t*       kvn  = (uint8_t*)(arena + 4 * MB);    // 8 MB fp8
    uint8_t*       wtb  = (uint8_t*)(arena + 20 * MB);   // 12 MB fp8 weights
    uint8_t*       Wqb  = wtb + 0u * (1u << 20);
    uint8_t*       Wkb  = wtb + 1u * (1u << 20);
    uint8_t*       Wvb  = wtb + 2u * (1u << 20);
    uint8_t*       Wob  = wtb + 3u * (1u << 20);
    uint8_t*       fc1b = wtb + 4u * (1u << 20);
    uint8_t*       fc2b = wtb + 8u * (1u << 20);
    __nv_bfloat16* qb   = (__nv_bfloat16*)(arena + 44 * MB);
    __nv_bfloat16* kb   = (__nv_bfloat16*)(arena + 48 * MB);
    __nv_bfloat16* vb   = (__nv_bfloat16*)(arena + 64 * MB);
    uint8_t*       ctx8 = (uint8_t*)(arena + 80 * MB);   // 2 MB fp8
    uint8_t*       hln  = (uint8_t*)(arena + 84 * MB);   // 2 MB fp8
    uint8_t*       h1b  = (uint8_t*)(arena + 88 * MB);   // 8 MB fp8
    float*         opart = (float*)(arena + 104 * MB);   // 16 MB
    float*         lpart = (float*)(arena + 120 * MB);   // 256 KB

    constexpr uint32_t kSmem128 = 3u * (128u + 128u) * 128u;  // 98304
    constexpr uint32_t kSmem64  = 3u * (128u + 64u) * 128u;   // 73728

    cudaFuncSetAttribute(qkv_gemm_kernel,
                         cudaFuncAttributeMaxDynamicSharedMemorySize, kSmem128);
    cudaFuncSetAttribute(gemm_fp8_kernel<1,128>,
                         cudaFuncAttributeMaxDynamicSharedMemorySize, kSmem128);
    cudaFuncSetAttribute(gemm_fp8_kernel<2,64>,
                         cudaFuncAttributeMaxDynamicSharedMemorySize, kSmem64);

    cvt_all_kernel<<<12288, 256>>>(Wq, Wk, Wv, Wo, fc1_w, fc2_w, wtb);

    ln_qkv_kernel<<<kNQ + kNKV, 256>>>(q_tokens, kv_tokens, q_ln_w, q_ln_b,
                                       kv_ln_w, kv_ln_b, qn, kvn);

    // merged Q/K/V projections (fp8 in -> bf16 out)
    qkv_gemm_kernel<<<1152, 128, kSmem128>>>(qn, kvn, Wqb, Wkb, Wvb, qb, kb, vb);

    // split-KV attention (bf16) + combine (fp8 ctx)
    attn_mma_kernel<<<dim3(kB * kH, kLq / 64, kSplits), 128>>>(qb, kb, vb, opart, lpart);
    attn_combine_kernel<<<kNQ, 256>>>(opart, lpart, ctx8);

    // out = q_tokens + alpha_attn * (ctx @ Wo^T + bo)
    gemm_fp8_kernel<2,64><<<dim3(kDim / 64, kNQ / 128), 128, kSmem64>>>(
        ctx8, Wob, kDim, kDim, bo, q_tokens, alpha_attn, out, nullptr, nullptr);

    ln_fp8_kernel<<<kNQ, 256>>>(out, mlp_ln_w, mlp_ln_b, hln);

    // h1 = gelu(hln @ fc1^T + b1) (fp8 out)
    gemm_fp8_kernel<1,128><<<dim3(kMlp / 128, kNQ / 128), 128, kSmem128>>>(
        hln, fc1b, kMlp, kDim, fc1_b, nullptr, nullptr, nullptr, nullptr, h1b);

    // out = out + alpha_mlp * (h1 @ fc2^T + b2)
    gemm_fp8_kernel<2,64><<<dim3(kDim / 64, kNQ / 128), 128, kSmem64>>>(
        h1b, fc2b, kDim, kMlp, fc2_b, out, alpha_mlp, out, nullptr, nullptr);
}